// round 13
// baseline (speedup 1.0000x reference)
#include <cuda_runtime.h>
#include <cuda_fp16.h>
#include <cstdint>

#define BB 2
#define TT 4096
#define HH 16
#define DD 128
#define HDIM 2048
#define O3 6144
#define NQG 8192
#define NCH 64
#define CH 64

typedef unsigned long long ull;

// ---------------- scratch (static device globals; no runtime allocation) ----
static __device__ float g_q[(size_t)BB * HH * TT * DD];       // (b,h,t,d)
static __device__ float g_k[(size_t)BB * HH * TT * DD];
static __device__ float g_v[(size_t)BB * HH * TT * DD];
static __device__ float g_o[(size_t)BB * HH * TT * DD];       // intra term
static __device__ float g_gate[(size_t)BB * TT * HDIM];       // sigmoid'ed, fp32
static __device__ float g_U[(size_t)BB * HH * NCH * DD * DD];
static __device__ float g_S[(size_t)BB * HH * NCH * DD * DD];
static __device__ float g_ct[(size_t)BB * TT * 32];
static __device__ float g_st[(size_t)BB * TT * 32];

// fp16 operands
static __device__ __half g_hh[(size_t)BB * TT * HDIM];
static __device__ __half g_wqh[(size_t)O3 * HDIM];
static __device__ __half g_wgh[(size_t)HDIM * HDIM];
static __device__ __half g_wdh[(size_t)HDIM * HDIM];
static __device__ __half g_onh[(size_t)BB * TT * HDIM];

__device__ __forceinline__ float head_slope(int h) {
    float a = (float)exp2(-0.5 * (double)(h + 1));
    return (float)(-(double)a * (1.0 - 11.0 / 31.0 + 1e-5));
}

__device__ __forceinline__ uint32_t s2u(const void* p) {
    uint32_t a;
    asm("{ .reg .u64 t; cvta.to.shared.u64 t, %1; cvt.u32.u64 %0, t; }" : "=r"(a) : "l"(p));
    return a;
}

__device__ __forceinline__ void cp16(uint32_t dst, const void* src) {
    asm volatile("cp.async.cg.shared.global [%0], [%1], 16;" :: "r"(dst), "l"(src));
}

__device__ __forceinline__ void ldsm4(uint32_t& r0, uint32_t& r1, uint32_t& r2, uint32_t& r3,
                                      uint32_t addr) {
    asm volatile("ldmatrix.sync.aligned.m8n8.x4.shared.b16 {%0,%1,%2,%3}, [%4];"
                 : "=r"(r0), "=r"(r1), "=r"(r2), "=r"(r3) : "r"(addr));
}

__device__ __forceinline__ void mma16816(float* c, const uint32_t* a, const uint32_t* b) {
    asm volatile(
        "mma.sync.aligned.m16n8k16.row.col.f32.f16.f16.f32 "
        "{%0,%1,%2,%3}, {%4,%5,%6,%7}, {%8,%9}, {%0,%1,%2,%3};"
        : "+f"(c[0]), "+f"(c[1]), "+f"(c[2]), "+f"(c[3])
        : "r"(a[0]), "r"(a[1]), "r"(a[2]), "r"(a[3]), "r"(b[0]), "r"(b[1]));
}

// ======================= fp16 mma.sync GEMM, 512 threads =====================
#define GPITCH 144
#define GA_BYTES (256 * GPITCH)
#define GB_BYTES (128 * GPITCH)
#define GSTG (GA_BYTES + GB_BYTES)
#define GNSTG 4
#define GCHUNKS 32

__global__ void __launch_bounds__(512, 1) gemm_f16(
    const __half* __restrict__ Am, const __half* __restrict__ Bm,
    const __half* __restrict__ Bm2,
    float* __restrict__ C, int Ntot, int mode,
    const float* __restrict__ qlnw, const float* __restrict__ klnw,
    float* __restrict__ outq, float* __restrict__ outk, float* __restrict__ outv) {
    extern __shared__ __align__(128) char smem[];
    const uint32_t sbase = s2u(smem);
    const int tid = threadIdx.x;
    const int lane = tid & 31;
    const int warp = tid >> 5;
    const int wy = warp & 7;
    const int wx = warp >> 3;
    const int m0 = blockIdx.y * 256;
    const int n0 = blockIdx.x * 128;

    const __half* Bbase = (mode == 2 && n0 >= O3)
                              ? Bm2 + (size_t)(n0 - O3) * 2048
                              : Bm + (size_t)n0 * 2048;

    float acc[2][8][4];
#pragma unroll
    for (int i = 0; i < 2; i++)
#pragma unroll
        for (int j = 0; j < 8; j++)
#pragma unroll
            for (int q = 0; q < 4; q++) acc[i][j][q] = 0.f;

#define LOAD_CHUNK(c, s)                                                                \
    do {                                                                                \
        int _kk = (c) << 6;                                                             \
        const __half* _Ab = Am + (size_t)m0 * 2048 + _kk;                               \
        const __half* _Bb = Bbase + _kk;                                                \
        uint32_t _sa = sbase + (s) * GSTG;                                              \
        uint32_t _sb = _sa + GA_BYTES;                                                  \
        _Pragma("unroll") for (int t = 0; t < 4; t++) {                                 \
            int idx = tid + t * 512;                                                    \
            int row = idx >> 3, ch = idx & 7;                                           \
            cp16(_sa + row * GPITCH + ch * 16, _Ab + (size_t)row * 2048 + ch * 8);      \
        }                                                                               \
        _Pragma("unroll") for (int t = 0; t < 2; t++) {                                 \
            int idx = tid + t * 512;                                                    \
            int row = idx >> 3, ch = idx & 7;                                           \
            cp16(_sb + row * GPITCH + ch * 16, _Bb + (size_t)row * 2048 + ch * 8);      \
        }                                                                               \
    } while (0)

    for (int c = 0; c < 3; c++) {
        LOAD_CHUNK(c, c);
        asm volatile("cp.async.commit_group;" ::: "memory");
    }

    const uint32_t aoff = (uint32_t)(wy * 32 + (lane & 15)) * GPITCH + (lane >> 4) * 16;
    const int brow = (lane & 7) + ((lane >> 4) << 3);
    const uint32_t boff0 = GA_BYTES + (uint32_t)(wx * 64 + brow) * GPITCH + ((lane >> 3) & 1) * 16;

    for (int i = 0; i < GCHUNKS; i++) {
        const int s = i & 3;
        asm volatile("cp.async.wait_group 2;" ::: "memory");
        __syncthreads();
        {
            const int j = i + 3;
            if (j < GCHUNKS) LOAD_CHUNK(j, j & 3);
        }
        asm volatile("cp.async.commit_group;" ::: "memory");
        const uint32_t sa = sbase + s * GSTG;

#pragma unroll
        for (int ks = 0; ks < 4; ks++) {
            uint32_t a[2][4], b[4][2];
#pragma unroll
            for (int mt = 0; mt < 2; mt++)
                ldsm4(a[mt][0], a[mt][1], a[mt][2], a[mt][3],
                      sa + aoff + mt * 16 * GPITCH + ks * 32);
            ldsm4(b[0][0], b[0][1], b[1][0], b[1][1], sa + boff0 + ks * 32);
            ldsm4(b[2][0], b[2][1], b[3][0], b[3][1], sa + boff0 + 16 * GPITCH + ks * 32);
#pragma unroll
            for (int mt = 0; mt < 2; mt++)
#pragma unroll
                for (int nt = 0; nt < 4; nt++)
                    mma16816(acc[mt][nt * 2 + 0], a[mt], b[nt]);
            ldsm4(b[0][0], b[0][1], b[1][0], b[1][1], sa + boff0 + 32 * GPITCH + ks * 32);
            ldsm4(b[2][0], b[2][1], b[3][0], b[3][1], sa + boff0 + 48 * GPITCH + ks * 32);
#pragma unroll
            for (int mt = 0; mt < 2; mt++)
#pragma unroll
                for (int nt = 0; nt < 4; nt++)
                    mma16816(acc[mt][nt * 2 + 1], a[mt], b[nt]);
        }
    }

    asm volatile("cp.async.wait_group 0;" ::: "memory");
    __syncthreads();

    const int seg = (mode == 2) ? (n0 >> 11) : -1;

    if (mode == 2 && seg < 3) {
        const int h = (n0 >> 7) & 15;
        float* rbuf = (float*)smem;

        if (seg < 2) {
#pragma unroll
            for (int mt = 0; mt < 2; mt++)
#pragma unroll
                for (int rh = 0; rh < 2; rh++) {
                    float p = 0.f;
#pragma unroll
                    for (int j = 0; j < 8; j++) {
                        float a0 = acc[mt][j][rh * 2], a1 = acc[mt][j][rh * 2 + 1];
                        p += a0 * a0 + a1 * a1;
                    }
                    p += __shfl_xor_sync(0xffffffffu, p, 1);
                    p += __shfl_xor_sync(0xffffffffu, p, 2);
                    if ((lane & 3) == 0)
                        rbuf[wx * 256 + wy * 32 + (lane >> 2) + mt * 16 + rh * 8] = p;
                }
            __syncthreads();
        }

        const float* lnw = (seg == 0) ? qlnw : klnw;
        float* dstbase = (seg == 0) ? outq : ((seg == 1) ? outk : outv);
        const float segscale = (seg == 0) ? 0.08838834764831845f : 1.0f;

#pragma unroll
        for (int mt = 0; mt < 2; mt++) {
#pragma unroll
            for (int rh = 0; rh < 2; rh++) {
                const int rloc = wy * 32 + (lane >> 2) + mt * 16 + rh * 8;
                const int r = m0 + rloc;
                const int b = r >> 12, t = r & 4095;
                float rq = 1.f;
                if (seg < 2)
                    rq = rsqrtf((rbuf[rloc] + rbuf[256 + rloc]) * (1.f / 128.f) + 1e-6f);

                float vals[16];
#pragma unroll
                for (int j = 0; j < 8; j++) {
                    int ld = wx * 64 + (j & 1) * 32 + (j >> 1) * 8 + (lane & 3) * 2;
                    float v0 = acc[mt][j][rh * 2], v1 = acc[mt][j][rh * 2 + 1];
                    if (seg < 2) {
                        v0 *= rq * lnw[ld];
                        v1 *= rq * lnw[ld + 1];
                    }
                    vals[j * 2] = v0;
                    vals[j * 2 + 1] = v1;
                }
                if (seg < 2 && wx == 0) {
#pragma unroll
                    for (int nt = 0; nt < 4; nt++) {
                        int d = nt * 8 + (lane & 3) * 2;
                        float2 c2 = *(const float2*)&g_ct[(size_t)r * 32 + d];
                        float2 s2 = *(const float2*)&g_st[(size_t)r * 32 + d];
                        float e0 = vals[nt * 4 + 0], e1 = vals[nt * 4 + 1];
                        float o0 = vals[nt * 4 + 2], o1 = vals[nt * 4 + 3];
                        vals[nt * 4 + 0] = e0 * c2.x - o0 * s2.x;
                        vals[nt * 4 + 1] = e1 * c2.y - o1 * s2.y;
                        vals[nt * 4 + 2] = o0 * c2.x + e0 * s2.x;
                        vals[nt * 4 + 3] = o1 * c2.y + e1 * s2.y;
                    }
                }
                size_t obase = ((size_t)(b * HH + h) * TT + t) * DD;
#pragma unroll
                for (int j = 0; j < 8; j++) {
                    int ld = wx * 64 + (j & 1) * 32 + (j >> 1) * 8 + (lane & 3) * 2;
                    *(float2*)(dstbase + obase + ld) =
                        make_float2(vals[j * 2] * segscale, vals[j * 2 + 1] * segscale);
                }
            }
        }
    } else {
        const int act = (seg == 3);
        const int ncol0 = (seg == 3) ? (n0 - O3) : n0;
        const int rbase = m0 + wy * 32 + (lane >> 2);
        const int cbase = ncol0 + wx * 64 + (lane & 3) * 2;
#pragma unroll
        for (int mt = 0; mt < 2; mt++) {
#pragma unroll
            for (int j = 0; j < 8; j++) {
                int nt = j >> 1, half = j & 1;
                int col = cbase + half * 32 + nt * 8;
                float v[4];
#pragma unroll
                for (int q = 0; q < 4; q++) {
                    float x = acc[mt][j][q];
                    v[q] = act ? (1.f / (1.f + expf(-x))) : x;
                }
                float* d0 = C + (size_t)(rbase + mt * 16) * Ntot + col;
                float* d1 = C + (size_t)(rbase + mt * 16 + 8) * Ntot + col;
                *(float2*)d0 = make_float2(v[0], v[1]);
                *(float2*)d1 = make_float2(v[2], v[3]);
            }
        }
    }
}

// ---------------- fp32 -> fp16 conversions ----------------------------------
#define CV_H (BB * TT * HDIM / 4)
#define CV_Q (O3 * HDIM / 4)
#define CV_G (HDIM * HDIM / 4)
#define CV_TOT (CV_H + CV_Q + 2 * CV_G)
__global__ void __launch_bounds__(256) k_cvt_all(const float* __restrict__ hidden,
                                                 const float* __restrict__ wq,
                                                 const float* __restrict__ wg,
                                                 const float* __restrict__ wd) {
    int i = blockIdx.x * 256 + threadIdx.x;
    const float* src;
    __half* dst;
    int off;
    if (i < CV_H) {
        src = hidden; dst = g_hh; off = i;
    } else if (i < CV_H + CV_Q) {
        src = wq; dst = g_wqh; off = i - CV_H;
    } else if (i < CV_H + CV_Q + CV_G) {
        src = wg; dst = g_wgh; off = i - CV_H - CV_Q;
    } else {
        src = wd; dst = g_wdh; off = i - CV_H - CV_Q - CV_G;
    }
    float4 x = ((const float4*)src)[off];
    __half h[4] = {__float2half(x.x), __float2half(x.y), __float2half(x.z), __float2half(x.w)};
    ((uint2*)dst)[off] = *(uint2*)h;
}

// ---------------- rope cos/sin table ----------------------------------------
__global__ void __launch_bounds__(256) k_rope_table(const int* __restrict__ pos) {
    int idx = blockIdx.x * 256 + threadIdx.x;
    int bt = idx >> 5, d = idx & 31;
    float p = (float)pos[bt];
    float inv = exp2f(-(float)d * 0.4152410118609203f);
    float sn, cs;
    sincosf(p * inv, &sn, &cs);
    g_ct[idx] = cs;
    g_st[idx] = sn;
}

// ========== pass A (HMMA): att(masked) / intra=att@v / U=(k*kdec)^T v ========
#define QP 136
#define VP 72
#define AP 72
#define HQ_H 0
#define HQ_L 8704
#define HK_H 17408
#define HK_L 26112
#define HV_H 34816
#define HV_L 44032
#define HD_H 53248
#define HD_L 62464
#define HA_H 71680
#define HA_L 76288
#define SMEM_CL (80896 * 2)

__global__ void __launch_bounds__(256, 1) k_chunk_local() {
    extern __shared__ __align__(128) char sm[];
    const uint32_t sb = s2u(sm);
    __half* hp = (__half*)sm;
    const int tid = threadIdx.x;
    const int lane = tid & 31, warp = tid >> 5;
    const int c = blockIdx.x & (NCH - 1);
    const int bh = blockIdx.x >> 6;
    const int h = bh & (HH - 1);
    const float slope = head_slope(h);
    const size_t tbase = ((size_t)bh * TT + c * CH) * DD;

#pragma unroll
    for (int l = 0; l < 8; l++) {
        int idx = tid + l * 256;
        int row = idx >> 5;
        int c0 = (idx & 31) << 2;
        float4 qa = *(const float4*)(g_q + tbase + row * DD + c0);
        float4 ka = *(const float4*)(g_k + tbase + row * DD + c0);
        float4 va = *(const float4*)(g_v + tbase + row * DD + c0);
        float kd = expf(slope * (float)(63 - row));
        float qf[4] = {qa.x, qa.y, qa.z, qa.w};
        float kf[4] = {ka.x, ka.y, ka.z, ka.w};
        float vf[4] = {va.x, va.y, va.z, va.w};
        __half hh[4], ll[4];
#pragma unroll
        for (int j = 0; j < 4; j++) {
            hh[j] = __float2half(qf[j]);
            ll[j] = __float2half(qf[j] - __half2float(hh[j]));
        }
        *(__half2*)(hp + HQ_H + row * QP + c0) = *(__half2*)&hh[0];
        *(__half2*)(hp + HQ_H + row * QP + c0 + 2) = *(__half2*)&hh[2];
        *(__half2*)(hp + HQ_L + row * QP + c0) = *(__half2*)&ll[0];
        *(__half2*)(hp + HQ_L + row * QP + c0 + 2) = *(__half2*)&ll[2];
#pragma unroll
        for (int j = 0; j < 4; j++) {
            hh[j] = __float2half(kf[j]);
            ll[j] = __float2half(kf[j] - __half2float(hh[j]));
        }
        *(__half2*)(hp + HK_H + row * QP + c0) = *(__half2*)&hh[0];
        *(__half2*)(hp + HK_H + row * QP + c0 + 2) = *(__half2*)&hh[2];
        *(__half2*)(hp + HK_L + row * QP + c0) = *(__half2*)&ll[0];
        *(__half2*)(hp + HK_L + row * QP + c0 + 2) = *(__half2*)&ll[2];
#pragma unroll
        for (int j = 0; j < 4; j++) {
            int d = c0 + j;
            __half vh = __float2half(vf[j]);
            hp[HV_H + d * VP + row] = vh;
            hp[HV_L + d * VP + row] = __float2half(vf[j] - __half2float(vh));
            float kv = kf[j] * kd;
            __half dh = __float2half(kv);
            hp[HD_H + d * VP + row] = dh;
            hp[HD_L + d * VP + row] = __float2half(kv - __half2float(dh));
        }
    }
    __syncthreads();

    const int wy = warp & 3, wx = warp >> 2;
    const int brow = (lane & 7) + ((lane >> 4) << 3);
    const uint32_t acol = (uint32_t)(lane >> 4) * 16;
    const uint32_t bcol = (uint32_t)((lane >> 3) & 1) * 16;

    {
        const uint32_t aqh = sb + HQ_H * 2 + ((wy * 16 + (lane & 15)) * QP) * 2 + acol;
        const uint32_t aql = aqh + (HQ_L - HQ_H) * 2;
        const uint32_t bkh0 = sb + HK_H * 2 + ((wx * 32 + brow) * QP) * 2 + bcol;
        const uint32_t bkh1 = bkh0 + 16 * QP * 2;
        const uint32_t bkl0 = bkh0 + (HK_L - HK_H) * 2;
        const uint32_t bkl1 = bkl0 + 16 * QP * 2;

        float ca[4][4];
#pragma unroll
        for (int j = 0; j < 4; j++)
#pragma unroll
            for (int q = 0; q < 4; q++) ca[j][q] = 0.f;

#pragma unroll
        for (int ks = 0; ks < 8; ks++) {
            const uint32_t ko = ks * 32;
            uint32_t Ah[4], Al[4], BH[4][2], BL[4][2];
            ldsm4(Ah[0], Ah[1], Ah[2], Ah[3], aqh + ko);
            ldsm4(Al[0], Al[1], Al[2], Al[3], aql + ko);
            ldsm4(BH[0][0], BH[0][1], BH[1][0], BH[1][1], bkh0 + ko);
            ldsm4(BH[2][0], BH[2][1], BH[3][0], BH[3][1], bkh1 + ko);
            ldsm4(BL[0][0], BL[0][1], BL[1][0], BL[1][1], bkl0 + ko);
            ldsm4(BL[2][0], BL[2][1], BL[3][0], BL[3][1], bkl1 + ko);
#pragma unroll
            for (int j = 0; j < 4; j++) {
                mma16816(ca[j], Ah, BH[j]);
                mma16816(ca[j], Al, BH[j]);
                mma16816(ca[j], Ah, BL[j]);
            }
        }

        const int r0 = wy * 16 + (lane >> 2);
#pragma unroll
        for (int j = 0; j < 4; j++) {
            int cj = wx * 32 + j * 8 + (lane & 3) * 2;
            float v00 = (r0 >= cj) ? ca[j][0] * expf(slope * (float)(r0 - cj)) : 0.f;
            float v01 = (r0 >= cj + 1) ? ca[j][1] * expf(slope * (float)(r0 - cj - 1)) : 0.f;
            int r1 = r0 + 8;
            float v10 = (r1 >= cj) ? ca[j][2] * expf(slope * (float)(r1 - cj)) : 0.f;
            float v11 = (r1 >= cj + 1) ? ca[j][3] * expf(slope * (float)(r1 - cj - 1)) : 0.f;
            __half h00 = __float2half(v00), h01 = __float2half(v01);
            __half h10 = __float2half(v10), h11 = __float2half(v11);
            __half l00 = __float2half(v00 - __half2float(h00));
            __half l01 = __float2half(v01 - __half2float(h01));
            __half l10 = __float2half(v10 - __half2float(h10));
            __half l11 = __float2half(v11 - __half2float(h11));
            __half ph0[2] = {h00, h01}, ph1[2] = {h10, h11};
            __half pl0[2] = {l00, l01}, pl1[2] = {l10, l11};
            *(__half2*)(hp + HA_H + r0 * AP + cj) = *(__half2*)ph0;
            *(__half2*)(hp + HA_H + r1 * AP + cj) = *(__half2*)ph1;
            *(__half2*)(hp + HA_L + r0 * AP + cj) = *(__half2*)pl0;
            *(__half2*)(hp + HA_L + r1 * AP + cj) = *(__half2*)pl1;
        }
    }
    __syncthreads();

    {
        const uint32_t aah = sb + HA_H * 2 + ((wy * 16 + (lane & 15)) * AP) * 2 + acol;
        const uint32_t aal = aah + (HA_L - HA_H) * 2;
        uint32_t adh[2], adl[2], bvh[4], bvl[4];
#pragma unroll
        for (int mb = 0; mb < 2; mb++) {
            adh[mb] = sb + HD_H * 2 + ((wy * 32 + mb * 16 + (lane & 15)) * VP) * 2 + acol;
            adl[mb] = adh[mb] + (HD_L - HD_H) * 2;
        }
#pragma unroll
        for (int g = 0; g < 4; g++) {
            bvh[g] = sb + HV_H * 2 + ((wx * 64 + g * 16 + brow) * VP) * 2 + bcol;
            bvl[g] = bvh[g] + (HV_L - HV_H) * 2;
        }

        float ci[8][4], cu[2][8][4];
#pragma unroll
        for (int j = 0; j < 8; j++)
#pragma unroll
            for (int q = 0; q < 4; q++) {
                ci[j][q] = 0.f;
                cu[0][j][q] = 0.f;
                cu[1][j][q] = 0.f;
            }

#pragma unroll
        for (int ks = 0; ks < 4; ks++) {
            const uint32_t ko = ks * 32;
            uint32_t BH[8][2], BL[8][2];
#pragma unroll
            for (int g = 0; g < 4; g++) {
                ldsm4(BH[2 * g][0], BH[2 * g][1], BH[2 * g + 1][0], BH[2 * g + 1][1],
                      bvh[g] + ko);
                ldsm4(BL[2 * g][0], BL[2 * g][1], BL[2 * g + 1][0], BL[2 * g + 1][1],
                      bvl[g] + ko);
            }
            uint32_t Aah[4], Aal[4], Dh[2][4], Dl[2][4];
            ldsm4(Aah[0], Aah[1], Aah[2], Aah[3], aah + ko);
            ldsm4(Aal[0], Aal[1], Aal[2], Aal[3], aal + ko);
#pragma unroll
            for (int mb = 0; mb < 2; mb++) {
                ldsm4(Dh[mb][0], Dh[mb][1], Dh[mb][2], Dh[mb][3], adh[mb] + ko);
                ldsm4(Dl[mb][0], Dl[mb][1], Dl[mb][2], Dl[mb][3], adl[mb] + ko);
            }
#pragma unroll
            for (int j = 0; j < 8; j++) {
                mma16816(ci[j], Aah, BH[j]);
                mma16816(ci[j], Aal, BH[j]);
                mma16816(ci[j], Aah, BL[j]);
#pragma unroll
                for (int mb = 0; mb < 2; mb++) {
                    mma16816(cu[mb][j], Dh[mb], BH[j]);
                    mma16816(cu[mb][j], Dl[mb], BH[j]);
                    mma16816(cu[mb][j], Dh[mb], BL[j]);
                }
            }
        }

        const int r0 = wy * 16 + (lane >> 2);
#pragma unroll
        for (int j = 0; j < 8; j++) {
            int d = wx * 64 + j * 8 + (lane & 3) * 2;
            *(float2*)(g_o + tbase + (size_t)r0 * DD + d) = make_float2(ci[j][0], ci[j][1]);
            *(float2*)(g_o + tbase + (size_t)(r0 + 8) * DD + d) = make_float2(ci[j][2], ci[j][3]);
        }
        const size_t ub = ((size_t)bh * NCH + c) * (DD * DD);
#pragma unroll
        for (int mb = 0; mb < 2; mb++) {
            int m0r = wy * 32 + mb * 16 + (lane >> 2);
#pragma unroll
            for (int j = 0; j < 8; j++) {
                int d = wx * 64 + j * 8 + (lane & 3) * 2;
                *(float2*)(g_U + ub + (size_t)m0r * DD + d) =
                    make_float2(cu[mb][j][0], cu[mb][j][1]);
                *(float2*)(g_U + ub + (size_t)(m0r + 8) * DD + d) =
                    make_float2(cu[mb][j][2], cu[mb][j][3]);
            }
        }
    }
}

// ---------------- pass B: decayed prefix scan (float4) -----------------------
__global__ void __launch_bounds__(256) k_scan() {
    int g = blockIdx.x * 256 + threadIdx.x;
    int bh = g >> 12;
    int de4 = g & 4095;
    float chdec = expf(head_slope(bh & (HH - 1)) * 64.f);
    size_t base = (size_t)bh * NCH * (DD * DD) + (size_t)de4 * 4;
    float4 s = make_float4(0.f, 0.f, 0.f, 0.f);
    for (int c = 0; c < NCH; c++) {
        size_t idx = base + (size_t)c * (DD * DD);
        *(float4*)(g_S + idx) = s;
        float4 u = *(const float4*)(g_U + idx);
        s.x = s.x * chdec + u.x;
        s.y = s.y * chdec + u.y;
        s.z = s.z * chdec + u.z;
        s.w = s.w * chdec + u.w;
    }
}

// ==== pass C (HMMA): inter = q @ S (3-term split), + intra, gnorm*gate =======
// smem: q hi/lo [64][IQP], S^T hi/lo [128][ISP]; rbuf reuse after MMA.
#define IQP 136
#define ISP 136
#define IQ_H 0
#define IQ_L 8704
#define IS_H 17408
#define IS_L 34816
#define SMEM_IN (52224 * 2)

__global__ void __launch_bounds__(256, 1) k_inter(const float* __restrict__ gnw) {
    extern __shared__ __align__(128) char smi[];
    const uint32_t sb = s2u(smi);
    __half* hp = (__half*)smi;
    const int tid = threadIdx.x;
    const int lane = tid & 31, warp = tid >> 5;
    const int c = blockIdx.x & (NCH - 1);
    const int bh = blockIdx.x >> 6;
    const int b = bh >> 4, h = bh & (HH - 1);
    const float slope = head_slope(h);
    const size_t tbase = ((size_t)bh * TT + c * CH) * DD;
    const size_t sbase = ((size_t)bh * NCH + c) * (DD * DD);

    // stage q -> hi/lo planes
#pragma unroll
    for (int l = 0; l < 8; l++) {
        int idx = tid + l * 256;
        int row = idx >> 5;
        int c0 = (idx & 31) << 2;
        float4 qa = *(const float4*)(g_q + tbase + row * DD + c0);
        float qf[4] = {qa.x, qa.y, qa.z, qa.w};
        __half hh[4], ll[4];
#pragma unroll
        for (int j = 0; j < 4; j++) {
            hh[j] = __float2half(qf[j]);
            ll[j] = __float2half(qf[j] - __half2float(hh[j]));
        }
        *(__half2*)(hp + IQ_H + row * IQP + c0) = *(__half2*)&hh[0];
        *(__half2*)(hp + IQ_H + row * IQP + c0 + 2) = *(__half2*)&hh[2];
        *(__half2*)(hp + IQ_L + row * IQP + c0) = *(__half2*)&ll[0];
        *(__half2*)(hp + IQ_L + row * IQP + c0 + 2) = *(__half2*)&ll[2];
    }
    // stage S transposed -> hi/lo planes
#pragma unroll
    for (int l = 0; l < 16; l++) {
        int idx = tid + l * 256;
        int di = idx >> 5;           // d_in row of S
        int c0 = (idx & 31) << 2;    // d_out
        float4 sa = *(const float4*)(g_S + sbase + (size_t)di * DD + c0);
        float sf[4] = {sa.x, sa.y, sa.z, sa.w};
#pragma unroll
        for (int j = 0; j < 4; j++) {
            int dn = c0 + j;
            __half sh = __float2half(sf[j]);
            hp[IS_H + dn * ISP + di] = sh;
            hp[IS_L + dn * ISP + di] = __float2half(sf[j] - __half2float(sh));
        }
    }
    __syncthreads();

    const int wy = warp & 3, wx = warp >> 2;
    const int brow = (lane & 7) + ((lane >> 4) << 3);
    const uint32_t acol = (uint32_t)(lane >> 4) * 16;
    const uint32_t bcol = (uint32_t)((lane >> 3) & 1) * 16;

    const uint32_t aah = sb + IQ_H * 2 + ((wy * 16 + (lane & 15)) * IQP) * 2 + acol;
    const uint32_t aal = aah + (IQ_L - IQ_H) * 2;
    uint32_t bsh[4], bsl[4];
#pragma unroll
    for (int g = 0; g < 4; g++) {
        bsh[g] = sb + IS_H * 2 + ((wx * 64 + g * 16 + brow) * ISP) * 2 + bcol;
        bsl[g] = bsh[g] + (IS_L - IS_H) * 2;
    }

    float ci[8][4];
#pragma unroll
    for (int j = 0; j < 8; j++)
#pragma unroll
        for (int q = 0; q < 4; q++) ci[j][q] = 0.f;

#pragma unroll
    for (int ks = 0; ks < 8; ks++) {
        const uint32_t ko = ks * 32;
        uint32_t Ah[4], Al[4], BH[8][2], BL[8][2];
        ldsm4(Ah[0], Ah[1], Ah[2], Ah[3], aah + ko);
        ldsm4(Al[0], Al[1], Al[2], Al[3], aal + ko);
#pragma unroll
        for (int g = 0; g < 4; g++) {
            ldsm4(BH[2 * g][0], BH[2 * g][1], BH[2 * g + 1][0], BH[2 * g + 1][1], bsh[g] + ko);
            ldsm4(BL[2 * g][0], BL[2 * g][1], BL[2 * g + 1][0], BL[2 * g + 1][1], bsl[g] + ko);
        }
#pragma unroll
        for (int j = 0; j < 8; j++) {
            mma16816(ci[j], Ah, BH[j]);
            mma16816(ci[j], Al, BH[j]);
            mma16816(ci[j], Ah, BL[j]);
        }
    }

    __syncthreads();   // planes dead; reuse base as rbuf
    float* rbuf = (float*)smi;

    const int r0 = wy * 16 + (lane >> 2);
    const float qd0 = expf(slope * (float)(r0 + 1));
    const float qd1 = expf(slope * (float)(r0 + 9));

    // v = intra + qd * inter (in place in ci)
#pragma unroll
    for (int j = 0; j < 8; j++) {
        int d = wx * 64 + j * 8 + (lane & 3) * 2;
        float2 o0 = *(const float2*)(g_o + tbase + (size_t)r0 * DD + d);
        float2 o1 = *(const float2*)(g_o + tbase + (size_t)(r0 + 8) * DD + d);
        ci[j][0] = o0.x + ci[j][0] * qd0;
        ci[j][1] = o0.y + ci[j][1] * qd0;
        ci[j][2] = o1.x + ci[j][2] * qd1;
        ci[j][3] = o1.y + ci[j][3] * qd1;
    }

    // row sums of squares
    float p0 = 0.f, p1 = 0.f;
#pragma unroll
    for (int j = 0; j < 8; j++) {
        p0 += ci[j][0] * ci[j][0] + ci[j][1] * ci[j][1];
        p1 += ci[j][2] * ci[j][2] + ci[j][3] * ci[j][3];
    }
    p0 += __shfl_xor_sync(0xffffffffu, p0, 1);
    p0 += __shfl_xor_sync(0xffffffffu, p0, 2);
    p1 += __shfl_xor_sync(0xffffffffu, p1, 1);
    p1 += __shfl_xor_sync(0xffffffffu, p1, 2);
    if ((lane & 3) == 0) {
        rbuf[wx * 64 + r0] = p0;
        rbuf[wx * 64 + r0 + 8] = p1;
    }
    __syncthreads();
    const float rq0 = rsqrtf((rbuf[r0] + rbuf[64 + r0]) * (1.f / 128.f) + 1e-6f);
    const float rq1 = rsqrtf((rbuf[r0 + 8] + rbuf[64 + r0 + 8]) * (1.f / 128.f) + 1e-6f);

    const size_t bt0 = (size_t)b * TT + c * CH + r0;
    const size_t bt1 = bt0 + 8;
#pragma unroll
    for (int j = 0; j < 8; j++) {
        int d = wx * 64 + j * 8 + (lane & 3) * 2;
        float2 w = *(const float2*)&gnw[h * DD + d];
        float2 gA = *(const float2*)(g_gate + bt0 * HDIM + h * DD + d);
        float2 gB = *(const float2*)(g_gate + bt1 * HDIM + h * DD + d);
        __half o0[2] = {__float2half(ci[j][0] * rq0 * w.x * gA.x),
                        __float2half(ci[j][1] * rq0 * w.y * gA.y)};
        __half o1[2] = {__float2half(ci[j][2] * rq1 * w.x * gB.x),
                        __float2half(ci[j][3] * rq1 * w.y * gB.y)};
        *(__half2*)(g_onh + bt0 * HDIM + h * DD + d) = *(__half2*)o0;
        *(__half2*)(g_onh + bt1 * HDIM + h * DD + d) = *(__half2*)o1;
    }
}

// -----------------------------------------------------------------------------
extern "C" void kernel_launch(void* const* d_in, const int* in_sizes, int n_in,
                              void* d_out, int out_size) {
    const float* hidden = (const float*)d_in[0];
    const float* w_qkv = (const float*)d_in[1];
    const float* q_ln_w = (const float*)d_in[2];
    const float* k_ln_w = (const float*)d_in[3];
    const float* g_norm_w = (const float*)d_in[4];
    const float* w_g_proj = (const float*)d_in[5];
    const float* w_dense = (const float*)d_in[6];
    const int* pos = (const int*)d_in[7];
    float* out = (float*)d_out;

    void *p_gate, *p_hh, *p_wqh, *p_wgh, *p_wdh, *p_onh, *p_q, *p_k, *p_v;
    cudaGetSymbolAddress(&p_gate, g_gate);
    cudaGetSymbolAddress(&p_hh, g_hh);
    cudaGetSymbolAddress(&p_wqh, g_wqh);
    cudaGetSymbolAddress(&p_wgh, g_wgh);
    cudaGetSymbolAddress(&p_wdh, g_wdh);
    cudaGetSymbolAddress(&p_onh, g_onh);
    cudaGetSymbolAddress(&p_q, g_q);
    cudaGetSymbolAddress(&p_k, g_k);
    cudaGetSymbolAddress(&p_v, g_v);

    const int smemG = GNSTG * GSTG;  // 221184
    cudaFuncSetAttribute(k_chunk_local, cudaFuncAttributeMaxDynamicSharedMemorySize, SMEM_CL);
    cudaFuncSetAttribute(k_inter, cudaFuncAttributeMaxDynamicSharedMemorySize, SMEM_IN);
    cudaFuncSetAttribute(gemm_f16, cudaFuncAttributeMaxDynamicSharedMemorySize, smemG);

    // 0: all fp32->fp16 conversions
    k_cvt_all<<<CV_TOT / 256, 256>>>(hidden, w_qkv, w_g_proj, w_dense);
    // 1: rope table
    k_rope_table<<<(BB * TT * 32) / 256, 256>>>(pos);
    // 2: merged qkv+gate GEMM
    gemm_f16<<<dim3(NQG / 128, (BB * TT) / 256), 512, smemG>>>(
        (const __half*)p_hh, (const __half*)p_wqh, (const __half*)p_wgh,
        (float*)p_gate, HDIM, 2,
        q_ln_w, k_ln_w, (float*)p_q, (float*)p_k, (float*)p_v);
    // 3: per-chunk local (HMMA att/intra/U)  [ncu profile slot]
    k_chunk_local<<<BB * HH * NCH, 256, SMEM_CL>>>();
    // 4: decayed prefix scan
    k_scan<<<(BB * HH * DD * DD / 4) / 256, 256>>>();
    // 5: inter (HMMA) + fused group-rmsnorm * gate -> onh fp16
    k_inter<<<BB * HH * NCH, 256, SMEM_IN>>>(g_norm_w);
    // 6: out = on @ w_dense^T
    gemm_f16<<<dim3(HDIM / 128, (BB * TT) / 256), 512, smemG>>>(
        (const __half*)p_onh, (const __half*)p_wdh, nullptr, out, HDIM, 0,
        nullptr, nullptr, nullptr, nullptr, nullptr);
}

// round 16
// speedup vs baseline: 1.1213x; 1.1213x over previous
#include <cuda_runtime.h>
#include <cuda_fp16.h>
#include <cstdint>

#define BB 2
#define TT 4096
#define HH 16
#define DD 128
#define HDIM 2048
#define O3 6144
#define NQG 8192
#define NCH 64
#define CH 64

typedef unsigned long long ull;

// ---------------- scratch (static device globals; no runtime allocation) ----
static __device__ float g_q[(size_t)BB * HH * TT * DD];       // (b,h,t,d)
static __device__ float g_k[(size_t)BB * HH * TT * DD];
static __device__ float g_v[(size_t)BB * HH * TT * DD];
static __device__ float g_o[(size_t)BB * HH * TT * DD];       // intra term
static __device__ float g_gate[(size_t)BB * TT * HDIM];       // sigmoid'ed, fp32
static __device__ float g_U[(size_t)BB * HH * NCH * DD * DD];
static __device__ float g_S[(size_t)BB * HH * NCH * DD * DD];
static __device__ float g_ct[(size_t)BB * TT * 32];
static __device__ float g_st[(size_t)BB * TT * 32];

// fp16 operands
static __device__ __half g_hh[(size_t)BB * TT * HDIM];
static __device__ __half g_wqh[(size_t)O3 * HDIM];
static __device__ __half g_wgh[(size_t)HDIM * HDIM];
static __device__ __half g_wdh[(size_t)HDIM * HDIM];
static __device__ __half g_onh[(size_t)BB * TT * HDIM];

__device__ __forceinline__ float head_slope(int h) {
    float a = (float)exp2(-0.5 * (double)(h + 1));
    return (float)(-(double)a * (1.0 - 11.0 / 31.0 + 1e-5));
}

__device__ __forceinline__ uint32_t s2u(const void* p) {
    uint32_t a;
    asm("{ .reg .u64 t; cvta.to.shared.u64 t, %1; cvt.u32.u64 %0, t; }" : "=r"(a) : "l"(p));
    return a;
}

__device__ __forceinline__ void cp16(uint32_t dst, const void* src) {
    asm volatile("cp.async.cg.shared.global [%0], [%1], 16;" :: "r"(dst), "l"(src));
}

__device__ __forceinline__ void ldsm4(uint32_t& r0, uint32_t& r1, uint32_t& r2, uint32_t& r3,
                                      uint32_t addr) {
    asm volatile("ldmatrix.sync.aligned.m8n8.x4.shared.b16 {%0,%1,%2,%3}, [%4];"
                 : "=r"(r0), "=r"(r1), "=r"(r2), "=r"(r3) : "r"(addr));
}

__device__ __forceinline__ void mma16816(float* c, const uint32_t* a, const uint32_t* b) {
    asm volatile(
        "mma.sync.aligned.m16n8k16.row.col.f32.f16.f16.f32 "
        "{%0,%1,%2,%3}, {%4,%5,%6,%7}, {%8,%9}, {%0,%1,%2,%3};"
        : "+f"(c[0]), "+f"(c[1]), "+f"(c[2]), "+f"(c[3])
        : "r"(a[0]), "r"(a[1]), "r"(a[2]), "r"(a[3]), "r"(b[0]), "r"(b[1]));
}

// ======================= fp16 mma.sync GEMM, 512 threads =====================
#define GPITCH 144
#define GA_BYTES (256 * GPITCH)
#define GB_BYTES (128 * GPITCH)
#define GSTG (GA_BYTES + GB_BYTES)
#define GNSTG 4
#define GCHUNKS 32

__global__ void __launch_bounds__(512, 1) gemm_f16(
    const __half* __restrict__ Am, const __half* __restrict__ Bm,
    const __half* __restrict__ Bm2,
    float* __restrict__ C, int Ntot, int mode,
    const float* __restrict__ qlnw, const float* __restrict__ klnw,
    float* __restrict__ outq, float* __restrict__ outk, float* __restrict__ outv) {
    extern __shared__ __align__(128) char smem[];
    const uint32_t sbase = s2u(smem);
    const int tid = threadIdx.x;
    const int lane = tid & 31;
    const int warp = tid >> 5;
    const int wy = warp & 7;
    const int wx = warp >> 3;
    const int m0 = blockIdx.y * 256;
    const int n0 = blockIdx.x * 128;

    const __half* Bbase = (mode == 2 && n0 >= O3)
                              ? Bm2 + (size_t)(n0 - O3) * 2048
                              : Bm + (size_t)n0 * 2048;

    float acc[2][8][4];
#pragma unroll
    for (int i = 0; i < 2; i++)
#pragma unroll
        for (int j = 0; j < 8; j++)
#pragma unroll
            for (int q = 0; q < 4; q++) acc[i][j][q] = 0.f;

#define LOAD_CHUNK(c, s)                                                                \
    do {                                                                                \
        int _kk = (c) << 6;                                                             \
        const __half* _Ab = Am + (size_t)m0 * 2048 + _kk;                               \
        const __half* _Bb = Bbase + _kk;                                                \
        uint32_t _sa = sbase + (s) * GSTG;                                              \
        uint32_t _sb = _sa + GA_BYTES;                                                  \
        _Pragma("unroll") for (int t = 0; t < 4; t++) {                                 \
            int idx = tid + t * 512;                                                    \
            int row = idx >> 3, ch = idx & 7;                                           \
            cp16(_sa + row * GPITCH + ch * 16, _Ab + (size_t)row * 2048 + ch * 8);      \
        }                                                                               \
        _Pragma("unroll") for (int t = 0; t < 2; t++) {                                 \
            int idx = tid + t * 512;                                                    \
            int row = idx >> 3, ch = idx & 7;                                           \
            cp16(_sb + row * GPITCH + ch * 16, _Bb + (size_t)row * 2048 + ch * 8);      \
        }                                                                               \
    } while (0)

    for (int c = 0; c < 3; c++) {
        LOAD_CHUNK(c, c);
        asm volatile("cp.async.commit_group;" ::: "memory");
    }

    const uint32_t aoff = (uint32_t)(wy * 32 + (lane & 15)) * GPITCH + (lane >> 4) * 16;
    const int brow = (lane & 7) + ((lane >> 4) << 3);
    const uint32_t boff0 = GA_BYTES + (uint32_t)(wx * 64 + brow) * GPITCH + ((lane >> 3) & 1) * 16;

    for (int i = 0; i < GCHUNKS; i++) {
        const int s = i & 3;
        asm volatile("cp.async.wait_group 2;" ::: "memory");
        __syncthreads();
        {
            const int j = i + 3;
            if (j < GCHUNKS) LOAD_CHUNK(j, j & 3);
        }
        asm volatile("cp.async.commit_group;" ::: "memory");
        const uint32_t sa = sbase + s * GSTG;

#pragma unroll
        for (int ks = 0; ks < 4; ks++) {
            uint32_t a[2][4], b[4][2];
#pragma unroll
            for (int mt = 0; mt < 2; mt++)
                ldsm4(a[mt][0], a[mt][1], a[mt][2], a[mt][3],
                      sa + aoff + mt * 16 * GPITCH + ks * 32);
            ldsm4(b[0][0], b[0][1], b[1][0], b[1][1], sa + boff0 + ks * 32);
            ldsm4(b[2][0], b[2][1], b[3][0], b[3][1], sa + boff0 + 16 * GPITCH + ks * 32);
#pragma unroll
            for (int mt = 0; mt < 2; mt++)
#pragma unroll
                for (int nt = 0; nt < 4; nt++)
                    mma16816(acc[mt][nt * 2 + 0], a[mt], b[nt]);
            ldsm4(b[0][0], b[0][1], b[1][0], b[1][1], sa + boff0 + 32 * GPITCH + ks * 32);
            ldsm4(b[2][0], b[2][1], b[3][0], b[3][1], sa + boff0 + 48 * GPITCH + ks * 32);
#pragma unroll
            for (int mt = 0; mt < 2; mt++)
#pragma unroll
                for (int nt = 0; nt < 4; nt++)
                    mma16816(acc[mt][nt * 2 + 1], a[mt], b[nt]);
        }
    }

    asm volatile("cp.async.wait_group 0;" ::: "memory");
    __syncthreads();

    const int seg = (mode == 2) ? (n0 >> 11) : -1;

    if (mode == 2 && seg < 3) {
        const int h = (n0 >> 7) & 15;
        float* rbuf = (float*)smem;

        if (seg < 2) {
#pragma unroll
            for (int mt = 0; mt < 2; mt++)
#pragma unroll
                for (int rh = 0; rh < 2; rh++) {
                    float p = 0.f;
#pragma unroll
                    for (int j = 0; j < 8; j++) {
                        float a0 = acc[mt][j][rh * 2], a1 = acc[mt][j][rh * 2 + 1];
                        p += a0 * a0 + a1 * a1;
                    }
                    p += __shfl_xor_sync(0xffffffffu, p, 1);
                    p += __shfl_xor_sync(0xffffffffu, p, 2);
                    if ((lane & 3) == 0)
                        rbuf[wx * 256 + wy * 32 + (lane >> 2) + mt * 16 + rh * 8] = p;
                }
            __syncthreads();
        }

        const float* lnw = (seg == 0) ? qlnw : klnw;
        float* dstbase = (seg == 0) ? outq : ((seg == 1) ? outk : outv);
        const float segscale = (seg == 0) ? 0.08838834764831845f : 1.0f;

#pragma unroll
        for (int mt = 0; mt < 2; mt++) {
#pragma unroll
            for (int rh = 0; rh < 2; rh++) {
                const int rloc = wy * 32 + (lane >> 2) + mt * 16 + rh * 8;
                const int r = m0 + rloc;
                const int b = r >> 12, t = r & 4095;
                float rq = 1.f;
                if (seg < 2)
                    rq = rsqrtf((rbuf[rloc] + rbuf[256 + rloc]) * (1.f / 128.f) + 1e-6f);

                float vals[16];
#pragma unroll
                for (int j = 0; j < 8; j++) {
                    int ld = wx * 64 + (j & 1) * 32 + (j >> 1) * 8 + (lane & 3) * 2;
                    float v0 = acc[mt][j][rh * 2], v1 = acc[mt][j][rh * 2 + 1];
                    if (seg < 2) {
                        v0 *= rq * lnw[ld];
                        v1 *= rq * lnw[ld + 1];
                    }
                    vals[j * 2] = v0;
                    vals[j * 2 + 1] = v1;
                }
                if (seg < 2 && wx == 0) {
#pragma unroll
                    for (int nt = 0; nt < 4; nt++) {
                        int d = nt * 8 + (lane & 3) * 2;
                        float2 c2 = *(const float2*)&g_ct[(size_t)r * 32 + d];
                        float2 s2 = *(const float2*)&g_st[(size_t)r * 32 + d];
                        float e0 = vals[nt * 4 + 0], e1 = vals[nt * 4 + 1];
                        float o0 = vals[nt * 4 + 2], o1 = vals[nt * 4 + 3];
                        vals[nt * 4 + 0] = e0 * c2.x - o0 * s2.x;
                        vals[nt * 4 + 1] = e1 * c2.y - o1 * s2.y;
                        vals[nt * 4 + 2] = o0 * c2.x + e0 * s2.x;
                        vals[nt * 4 + 3] = o1 * c2.y + e1 * s2.y;
                    }
                }
                size_t obase = ((size_t)(b * HH + h) * TT + t) * DD;
#pragma unroll
                for (int j = 0; j < 8; j++) {
                    int ld = wx * 64 + (j & 1) * 32 + (j >> 1) * 8 + (lane & 3) * 2;
                    *(float2*)(dstbase + obase + ld) =
                        make_float2(vals[j * 2] * segscale, vals[j * 2 + 1] * segscale);
                }
            }
        }
    } else {
        const int act = (seg == 3);
        const int ncol0 = (seg == 3) ? (n0 - O3) : n0;
        const int rbase = m0 + wy * 32 + (lane >> 2);
        const int cbase = ncol0 + wx * 64 + (lane & 3) * 2;
#pragma unroll
        for (int mt = 0; mt < 2; mt++) {
#pragma unroll
            for (int j = 0; j < 8; j++) {
                int nt = j >> 1, half = j & 1;
                int col = cbase + half * 32 + nt * 8;
                float v[4];
#pragma unroll
                for (int q = 0; q < 4; q++) {
                    float x = acc[mt][j][q];
                    v[q] = act ? (1.f / (1.f + expf(-x))) : x;
                }
                float* d0 = C + (size_t)(rbase + mt * 16) * Ntot + col;
                float* d1 = C + (size_t)(rbase + mt * 16 + 8) * Ntot + col;
                *(float2*)d0 = make_float2(v[0], v[1]);
                *(float2*)d1 = make_float2(v[2], v[3]);
            }
        }
    }
}

// ---------------- fp32 -> fp16 conversions ----------------------------------
#define CV_H (BB * TT * HDIM / 4)
#define CV_Q (O3 * HDIM / 4)
#define CV_G (HDIM * HDIM / 4)
#define CV_TOT (CV_H + CV_Q + 2 * CV_G)
__global__ void __launch_bounds__(256) k_cvt_all(const float* __restrict__ hidden,
                                                 const float* __restrict__ wq,
                                                 const float* __restrict__ wg,
                                                 const float* __restrict__ wd) {
    int i = blockIdx.x * 256 + threadIdx.x;
    const float* src;
    __half* dst;
    int off;
    if (i < CV_H) {
        src = hidden; dst = g_hh; off = i;
    } else if (i < CV_H + CV_Q) {
        src = wq; dst = g_wqh; off = i - CV_H;
    } else if (i < CV_H + CV_Q + CV_G) {
        src = wg; dst = g_wgh; off = i - CV_H - CV_Q;
    } else {
        src = wd; dst = g_wdh; off = i - CV_H - CV_Q - CV_G;
    }
    float4 x = ((const float4*)src)[off];
    __half h[4] = {__float2half(x.x), __float2half(x.y), __float2half(x.z), __float2half(x.w)};
    ((uint2*)dst)[off] = *(uint2*)h;
}

// ---------------- rope cos/sin table ----------------------------------------
__global__ void __launch_bounds__(256) k_rope_table(const int* __restrict__ pos) {
    int idx = blockIdx.x * 256 + threadIdx.x;
    int bt = idx >> 5, d = idx & 31;
    float p = (float)pos[bt];
    float inv = exp2f(-(float)d * 0.4152410118609203f);
    float sn, cs;
    sincosf(p * inv, &sn, &cs);
    g_ct[idx] = cs;
    g_st[idx] = sn;
}

// ========== pass A (HMMA): att(masked) / intra=att@v / U=(k*kdec)^T v ========
#define QP 136
#define VP 72
#define AP 72
#define HQ_H 0
#define HQ_L 8704
#define HK_H 17408
#define HK_L 26112
#define HV_H 34816
#define HV_L 44032
#define HD_H 53248
#define HD_L 62464
#define HA_H 71680
#define HA_L 76288
#define SMEM_CL (80896 * 2 + 256)

__global__ void __launch_bounds__(256, 1) k_chunk_local() {
    extern __shared__ __align__(128) char sm[];
    const uint32_t sb = s2u(sm);
    __half* hp = (__half*)sm;
    float* kdecs = (float*)(sm + 80896 * 2);
    const int tid = threadIdx.x;
    const int lane = tid & 31, warp = tid >> 5;
    const int c = blockIdx.x & (NCH - 1);
    const int bh = blockIdx.x >> 6;
    const int h = bh & (HH - 1);
    const float slope = head_slope(h);
    const size_t tbase = ((size_t)bh * TT + c * CH) * DD;

    if (tid < 64) kdecs[tid] = expf(slope * (float)(63 - tid));

    // loop A: q, k row-major hi/lo planes
#pragma unroll
    for (int l = 0; l < 8; l++) {
        int idx = tid + l * 256;
        int row = idx >> 5;
        int c0 = (idx & 31) << 2;
        float4 qa = *(const float4*)(g_q + tbase + row * DD + c0);
        float4 ka = *(const float4*)(g_k + tbase + row * DD + c0);
        float qf[4] = {qa.x, qa.y, qa.z, qa.w};
        float kf[4] = {ka.x, ka.y, ka.z, ka.w};
        __half hh[4], ll[4];
#pragma unroll
        for (int j = 0; j < 4; j++) {
            hh[j] = __float2half(qf[j]);
            ll[j] = __float2half(qf[j] - __half2float(hh[j]));
        }
        *(uint2*)(hp + HQ_H + row * QP + c0) = *(uint2*)hh;
        *(uint2*)(hp + HQ_L + row * QP + c0) = *(uint2*)ll;
#pragma unroll
        for (int j = 0; j < 4; j++) {
            hh[j] = __float2half(kf[j]);
            ll[j] = __float2half(kf[j] - __half2float(hh[j]));
        }
        *(uint2*)(hp + HK_H + row * QP + c0) = *(uint2*)hh;
        *(uint2*)(hp + HK_L + row * QP + c0) = *(uint2*)ll;
    }
    __syncthreads();

    // loop B: v, kd transposed planes — each thread owns (d, 4 consecutive t)
#pragma unroll
    for (int l = 0; l < 8; l++) {
        int idx = tid + l * 256;   // 2048 = 128 d x 16 t-groups
        int d = idx & 127;
        int tg = idx >> 7;
        __half vh[4], vl[4], dh[4], dl[4];
#pragma unroll
        for (int j = 0; j < 4; j++) {
            int t = tg * 4 + j;
            float vv = g_v[tbase + (size_t)t * DD + d];
            float kk = g_k[tbase + (size_t)t * DD + d] * kdecs[t];
            vh[j] = __float2half(vv);
            vl[j] = __float2half(vv - __half2float(vh[j]));
            dh[j] = __float2half(kk);
            dl[j] = __float2half(kk - __half2float(dh[j]));
        }
        *(uint2*)(hp + HV_H + d * VP + tg * 4) = *(uint2*)vh;
        *(uint2*)(hp + HV_L + d * VP + tg * 4) = *(uint2*)vl;
        *(uint2*)(hp + HD_H + d * VP + tg * 4) = *(uint2*)dh;
        *(uint2*)(hp + HD_L + d * VP + tg * 4) = *(uint2*)dl;
    }
    __syncthreads();

    const int wy = warp & 3, wx = warp >> 2;
    const int brow = (lane & 7) + ((lane >> 4) << 3);
    const uint32_t acol = (uint32_t)(lane >> 4) * 16;
    const uint32_t bcol = (uint32_t)((lane >> 3) & 1) * 16;

    {
        const uint32_t aqh = sb + HQ_H * 2 + ((wy * 16 + (lane & 15)) * QP) * 2 + acol;
        const uint32_t aql = aqh + (HQ_L - HQ_H) * 2;
        const uint32_t bkh0 = sb + HK_H * 2 + ((wx * 32 + brow) * QP) * 2 + bcol;
        const uint32_t bkh1 = bkh0 + 16 * QP * 2;
        const uint32_t bkl0 = bkh0 + (HK_L - HK_H) * 2;
        const uint32_t bkl1 = bkl0 + 16 * QP * 2;

        float ca[4][4];
#pragma unroll
        for (int j = 0; j < 4; j++)
#pragma unroll
            for (int q = 0; q < 4; q++) ca[j][q] = 0.f;

#pragma unroll
        for (int ks = 0; ks < 8; ks++) {
            const uint32_t ko = ks * 32;
            uint32_t Ah[4], Al[4], BH[4][2], BL[4][2];
            ldsm4(Ah[0], Ah[1], Ah[2], Ah[3], aqh + ko);
            ldsm4(Al[0], Al[1], Al[2], Al[3], aql + ko);
            ldsm4(BH[0][0], BH[0][1], BH[1][0], BH[1][1], bkh0 + ko);
            ldsm4(BH[2][0], BH[2][1], BH[3][0], BH[3][1], bkh1 + ko);
            ldsm4(BL[0][0], BL[0][1], BL[1][0], BL[1][1], bkl0 + ko);
            ldsm4(BL[2][0], BL[2][1], BL[3][0], BL[3][1], bkl1 + ko);
#pragma unroll
            for (int j = 0; j < 4; j++) {
                mma16816(ca[j], Ah, BH[j]);
                mma16816(ca[j], Al, BH[j]);
                mma16816(ca[j], Ah, BL[j]);
            }
        }

        const int r0 = wy * 16 + (lane >> 2);
#pragma unroll
        for (int j = 0; j < 4; j++) {
            int cj = wx * 32 + j * 8 + (lane & 3) * 2;
            float v00 = (r0 >= cj) ? ca[j][0] * expf(slope * (float)(r0 - cj)) : 0.f;
            float v01 = (r0 >= cj + 1) ? ca[j][1] * expf(slope * (float)(r0 - cj - 1)) : 0.f;
            int r1 = r0 + 8;
            float v10 = (r1 >= cj) ? ca[j][2] * expf(slope * (float)(r1 - cj)) : 0.f;
            float v11 = (r1 >= cj + 1) ? ca[j][3] * expf(slope * (float)(r1 - cj - 1)) : 0.f;
            __half h00 = __float2half(v00), h01 = __float2half(v01);
            __half h10 = __float2half(v10), h11 = __float2half(v11);
            __half l00 = __float2half(v00 - __half2float(h00));
            __half l01 = __float2half(v01 - __half2float(h01));
            __half l10 = __float2half(v10 - __half2float(h10));
            __half l11 = __float2half(v11 - __half2float(h11));
            __half ph0[2] = {h00, h01}, ph1[2] = {h10, h11};
            __half pl0[2] = {l00, l01}, pl1[2] = {l10, l11};
            *(__half2*)(hp + HA_H + r0 * AP + cj) = *(__half2*)ph0;
            *(__half2*)(hp + HA_H + r1 * AP + cj) = *(__half2*)ph1;
            *(__half2*)(hp + HA_L + r0 * AP + cj) = *(__half2*)pl0;
            *(__half2*)(hp + HA_L + r1 * AP + cj) = *(__half2*)pl1;
        }
    }
    __syncthreads();

    {
        const uint32_t aah = sb + HA_H * 2 + ((wy * 16 + (lane & 15)) * AP) * 2 + acol;
        const uint32_t aal = aah + (HA_L - HA_H) * 2;
        uint32_t adh[2], adl[2], bvh[4], bvl[4];
#pragma unroll
        for (int mb = 0; mb < 2; mb++) {
            adh[mb] = sb + HD_H * 2 + ((wy * 32 + mb * 16 + (lane & 15)) * VP) * 2 + acol;
            adl[mb] = adh[mb] + (HD_L - HD_H) * 2;
        }
#pragma unroll
        for (int g = 0; g < 4; g++) {
            bvh[g] = sb + HV_H * 2 + ((wx * 64 + g * 16 + brow) * VP) * 2 + bcol;
            bvl[g] = bvh[g] + (HV_L - HV_H) * 2;
        }

        float ci[8][4], cu[2][8][4];
#pragma unroll
        for (int j = 0; j < 8; j++)
#pragma unroll
            for (int q = 0; q < 4; q++) {
                ci[j][q] = 0.f;
                cu[0][j][q] = 0.f;
                cu[1][j][q] = 0.f;
            }

#pragma unroll
        for (int ks = 0; ks < 4; ks++) {
            const uint32_t ko = ks * 32;
            uint32_t BH[8][2], BL[8][2];
#pragma unroll
            for (int g = 0; g < 4; g++) {
                ldsm4(BH[2 * g][0], BH[2 * g][1], BH[2 * g + 1][0], BH[2 * g + 1][1],
                      bvh[g] + ko);
                ldsm4(BL[2 * g][0], BL[2 * g][1], BL[2 * g + 1][0], BL[2 * g + 1][1],
                      bvl[g] + ko);
            }
            uint32_t Aah[4], Aal[4], Dh[2][4], Dl[2][4];
            ldsm4(Aah[0], Aah[1], Aah[2], Aah[3], aah + ko);
            ldsm4(Aal[0], Aal[1], Aal[2], Aal[3], aal + ko);
#pragma unroll
            for (int mb = 0; mb < 2; mb++) {
                ldsm4(Dh[mb][0], Dh[mb][1], Dh[mb][2], Dh[mb][3], adh[mb] + ko);
                ldsm4(Dl[mb][0], Dl[mb][1], Dl[mb][2], Dl[mb][3], adl[mb] + ko);
            }
#pragma unroll
            for (int j = 0; j < 8; j++) {
                mma16816(ci[j], Aah, BH[j]);
                mma16816(ci[j], Aal, BH[j]);
                mma16816(ci[j], Aah, BL[j]);
#pragma unroll
                for (int mb = 0; mb < 2; mb++) {
                    mma16816(cu[mb][j], Dh[mb], BH[j]);
                    mma16816(cu[mb][j], Dl[mb], BH[j]);
                    mma16816(cu[mb][j], Dh[mb], BL[j]);
                }
            }
        }

        const int r0 = wy * 16 + (lane >> 2);
#pragma unroll
        for (int j = 0; j < 8; j++) {
            int d = wx * 64 + j * 8 + (lane & 3) * 2;
            *(float2*)(g_o + tbase + (size_t)r0 * DD + d) = make_float2(ci[j][0], ci[j][1]);
            *(float2*)(g_o + tbase + (size_t)(r0 + 8) * DD + d) = make_float2(ci[j][2], ci[j][3]);
        }
        const size_t ub = ((size_t)bh * NCH + c) * (DD * DD);
#pragma unroll
        for (int mb = 0; mb < 2; mb++) {
            int m0r = wy * 32 + mb * 16 + (lane >> 2);
#pragma unroll
            for (int j = 0; j < 8; j++) {
                int d = wx * 64 + j * 8 + (lane & 3) * 2;
                *(float2*)(g_U + ub + (size_t)m0r * DD + d) =
                    make_float2(cu[mb][j][0], cu[mb][j][1]);
                *(float2*)(g_U + ub + (size_t)(m0r + 8) * DD + d) =
                    make_float2(cu[mb][j][2], cu[mb][j][3]);
            }
        }
    }
}

// ---------------- pass B: decayed prefix scan (float4) -----------------------
__global__ void __launch_bounds__(256) k_scan() {
    int g = blockIdx.x * 256 + threadIdx.x;
    int bh = g >> 12;
    int de4 = g & 4095;
    float chdec = expf(head_slope(bh & (HH - 1)) * 64.f);
    size_t base = (size_t)bh * NCH * (DD * DD) + (size_t)de4 * 4;
    float4 s = make_float4(0.f, 0.f, 0.f, 0.f);
    for (int c = 0; c < NCH; c++) {
        size_t idx = base + (size_t)c * (DD * DD);
        *(float4*)(g_S + idx) = s;
        float4 u = *(const float4*)(g_U + idx);
        s.x = s.x * chdec + u.x;
        s.y = s.y * chdec + u.y;
        s.z = s.z * chdec + u.z;
        s.w = s.w * chdec + u.w;
    }
}

// ==== pass C (HMMA): inter = q @ S (3-term split), + intra, gnorm*gate =======
#define IQP 136
#define ISP 136
#define IQ_H 0
#define IQ_L 8704
#define IS_H 17408
#define IS_L 34816
#define SMEM_IN (52224 * 2)

__global__ void __launch_bounds__(256, 1) k_inter(const float* __restrict__ gnw) {
    extern __shared__ __align__(128) char smi[];
    const uint32_t sb = s2u(smi);
    __half* hp = (__half*)smi;
    const int tid = threadIdx.x;
    const int lane = tid & 31, warp = tid >> 5;
    const int c = blockIdx.x & (NCH - 1);
    const int bh = blockIdx.x >> 6;
    const int b = bh >> 4, h = bh & (HH - 1);
    const float slope = head_slope(h);
    const size_t tbase = ((size_t)bh * TT + c * CH) * DD;
    const size_t sbase = ((size_t)bh * NCH + c) * (DD * DD);

    // stage q row-major hi/lo
#pragma unroll
    for (int l = 0; l < 8; l++) {
        int idx = tid + l * 256;
        int row = idx >> 5;
        int c0 = (idx & 31) << 2;
        float4 qa = *(const float4*)(g_q + tbase + row * DD + c0);
        float qf[4] = {qa.x, qa.y, qa.z, qa.w};
        __half hh[4], ll[4];
#pragma unroll
        for (int j = 0; j < 4; j++) {
            hh[j] = __float2half(qf[j]);
            ll[j] = __float2half(qf[j] - __half2float(hh[j]));
        }
        *(uint2*)(hp + IQ_H + row * IQP + c0) = *(uint2*)hh;
        *(uint2*)(hp + IQ_L + row * IQP + c0) = *(uint2*)ll;
    }
    // stage S transposed — thread owns (dn, 4 consecutive di), b64 stores
#pragma unroll
    for (int l = 0; l < 16; l++) {
        int idx = tid + l * 256;   // 4096 = 128 dn x 32 di-groups
        int dn = idx & 127;
        int dig = idx >> 7;
        __half sh[4], sl[4];
#pragma unroll
        for (int j = 0; j < 4; j++) {
            int di = dig * 4 + j;
            float s = g_S[sbase + (size_t)di * DD + dn];
            sh[j] = __float2half(s);
            sl[j] = __float2half(s - __half2float(sh[j]));
        }
        *(uint2*)(hp + IS_H + dn * ISP + dig * 4) = *(uint2*)sh;
        *(uint2*)(hp + IS_L + dn * ISP + dig * 4) = *(uint2*)sl;
    }
    __syncthreads();

    const int wy = warp & 3, wx = warp >> 2;
    const int brow = (lane & 7) + ((lane >> 4) << 3);
    const uint32_t acol = (uint32_t)(lane >> 4) * 16;
    const uint32_t bcol = (uint32_t)((lane >> 3) & 1) * 16;

    const uint32_t aah = sb + IQ_H * 2 + ((wy * 16 + (lane & 15)) * IQP) * 2 + acol;
    const uint32_t aal = aah + (IQ_L - IQ_H) * 2;
    uint32_t bsh[4], bsl[4];
#pragma unroll
    for (int g = 0; g < 4; g++) {
        bsh[g] = sb + IS_H * 2 + ((wx * 64 + g * 16 + brow) * ISP) * 2 + bcol;
        bsl[g] = bsh[g] + (IS_L - IS_H) * 2;
    }

    float ci[8][4];
#pragma unroll
    for (int j = 0; j < 8; j++)
#pragma unroll
        for (int q = 0; q < 4; q++) ci[j][q] = 0.f;

#pragma unroll
    for (int ks = 0; ks < 8; ks++) {
        const uint32_t ko = ks * 32;
        uint32_t Ah[4], Al[4], BH[8][2], BL[8][2];
        ldsm4(Ah[0], Ah[1], Ah[2], Ah[3], aah + ko);
        ldsm4(Al[0], Al[1], Al[2], Al[3], aal + ko);
#pragma unroll
        for (int g = 0; g < 4; g++) {
            ldsm4(BH[2 * g][0], BH[2 * g][1], BH[2 * g + 1][0], BH[2 * g + 1][1], bsh[g] + ko);
            ldsm4(BL[2 * g][0], BL[2 * g][1], BL[2 * g + 1][0], BL[2 * g + 1][1], bsl[g] + ko);
        }
#pragma unroll
        for (int j = 0; j < 8; j++) {
            mma16816(ci[j], Ah, BH[j]);
            mma16816(ci[j], Al, BH[j]);
            mma16816(ci[j], Ah, BL[j]);
        }
    }

    __syncthreads();
    float* rbuf = (float*)smi;

    const int r0 = wy * 16 + (lane >> 2);
    const float qd0 = expf(slope * (float)(r0 + 1));
    const float qd1 = expf(slope * (float)(r0 + 9));

#pragma unroll
    for (int j = 0; j < 8; j++) {
        int d = wx * 64 + j * 8 + (lane & 3) * 2;
        float2 o0 = *(const float2*)(g_o + tbase + (size_t)r0 * DD + d);
        float2 o1 = *(const float2*)(g_o + tbase + (size_t)(r0 + 8) * DD + d);
        ci[j][0] = o0.x + ci[j][0] * qd0;
        ci[j][1] = o0.y + ci[j][1] * qd0;
        ci[j][2] = o1.x + ci[j][2] * qd1;
        ci[j][3] = o1.y + ci[j][3] * qd1;
    }

    float p0 = 0.f, p1 = 0.f;
#pragma unroll
    for (int j = 0; j < 8; j++) {
        p0 += ci[j][0] * ci[j][0] + ci[j][1] * ci[j][1];
        p1 += ci[j][2] * ci[j][2] + ci[j][3] * ci[j][3];
    }
    p0 += __shfl_xor_sync(0xffffffffu, p0, 1);
    p0 += __shfl_xor_sync(0xffffffffu, p0, 2);
    p1 += __shfl_xor_sync(0xffffffffu, p1, 1);
    p1 += __shfl_xor_sync(0xffffffffu, p1, 2);
    if ((lane & 3) == 0) {
        rbuf[wx * 64 + r0] = p0;
        rbuf[wx * 64 + r0 + 8] = p1;
    }
    __syncthreads();
    const float rq0 = rsqrtf((rbuf[r0] + rbuf[64 + r0]) * (1.f / 128.f) + 1e-6f);
    const float rq1 = rsqrtf((rbuf[r0 + 8] + rbuf[64 + r0 + 8]) * (1.f / 128.f) + 1e-6f);

    const size_t bt0 = (size_t)b * TT + c * CH + r0;
    const size_t bt1 = bt0 + 8;
#pragma unroll
    for (int j = 0; j < 8; j++) {
        int d = wx * 64 + j * 8 + (lane & 3) * 2;
        float2 w = *(const float2*)&gnw[h * DD + d];
        float2 gA = *(const float2*)(g_gate + bt0 * HDIM + h * DD + d);
        float2 gB = *(const float2*)(g_gate + bt1 * HDIM + h * DD + d);
        __half o0[2] = {__float2half(ci[j][0] * rq0 * w.x * gA.x),
                        __float2half(ci[j][1] * rq0 * w.y * gA.y)};
        __half o1[2] = {__float2half(ci[j][2] * rq1 * w.x * gB.x),
                        __float2half(ci[j][3] * rq1 * w.y * gB.y)};
        *(__half2*)(g_onh + bt0 * HDIM + h * DD + d) = *(__half2*)o0;
        *(__half2*)(g_onh + bt1 * HDIM + h * DD + d) = *(__half2*)o1;
    }
}

// -----------------------------------------------------------------------------
extern "C" void kernel_launch(void* const* d_in, const int* in_sizes, int n_in,
                              void* d_out, int out_size) {
    const float* hidden = (const float*)d_in[0];
    const float* w_qkv = (const float*)d_in[1];
    const float* q_ln_w = (const float*)d_in[2];
    const float* k_ln_w = (const float*)d_in[3];
    const float* g_norm_w = (const float*)d_in[4];
    const float* w_g_proj = (const float*)d_in[5];
    const float* w_dense = (const float*)d_in[6];
    const int* pos = (const int*)d_in[7];
    float* out = (float*)d_out;

    void *p_gate, *p_hh, *p_wqh, *p_wgh, *p_wdh, *p_onh, *p_q, *p_k, *p_v;
    cudaGetSymbolAddress(&p_gate, g_gate);
    cudaGetSymbolAddress(&p_hh, g_hh);
    cudaGetSymbolAddress(&p_wqh, g_wqh);
    cudaGetSymbolAddress(&p_wgh, g_wgh);
    cudaGetSymbolAddress(&p_wdh, g_wdh);
    cudaGetSymbolAddress(&p_onh, g_onh);
    cudaGetSymbolAddress(&p_q, g_q);
    cudaGetSymbolAddress(&p_k, g_k);
    cudaGetSymbolAddress(&p_v, g_v);

    const int smemG = GNSTG * GSTG;  // 221184
    cudaFuncSetAttribute(k_chunk_local, cudaFuncAttributeMaxDynamicSharedMemorySize, SMEM_CL);
    cudaFuncSetAttribute(k_inter, cudaFuncAttributeMaxDynamicSharedMemorySize, SMEM_IN);
    cudaFuncSetAttribute(gemm_f16, cudaFuncAttributeMaxDynamicSharedMemorySize, smemG);

    // 0: all fp32->fp16 conversions
    k_cvt_all<<<CV_TOT / 256, 256>>>(hidden, w_qkv, w_g_proj, w_dense);
    // 1: rope table
    k_rope_table<<<(BB * TT * 32) / 256, 256>>>(pos);
    // 2: merged qkv+gate GEMM
    gemm_f16<<<dim3(NQG / 128, (BB * TT) / 256), 512, smemG>>>(
        (const __half*)p_hh, (const __half*)p_wqh, (const __half*)p_wgh,
        (float*)p_gate, HDIM, 2,
        q_ln_w, k_ln_w, (float*)p_q, (float*)p_k, (float*)p_v);
    // 3: per-chunk local (HMMA, conflict-fixed staging)  [ncu profile slot]
    k_chunk_local<<<BB * HH * NCH, 256, SMEM_CL>>>();
    // 4: decayed prefix scan
    k_scan<<<(BB * HH * DD * DD / 4) / 256, 256>>>();
    // 5: inter (HMMA, conflict-fixed staging) + gnorm*gate -> onh fp16
    k_inter<<<BB * HH * NCH, 256, SMEM_IN>>>(g_norm_w);
    // 6: out = on @ w_dense^T
    gemm_f16<<<dim3(HDIM / 128, (BB * TT) / 256), 512, smemG>>>(
        (const __half*)p_onh, (const __half*)p_wdh, nullptr, out, HDIM, 0,
        nullptr, nullptr, nullptr, nullptr, nullptr);
}